// round 3
// baseline (speedup 1.0000x reference)
#include <cuda_runtime.h>
#include <math.h>

#define BATCH  8
#define SEQ    1024
#define DMODEL 512
#define NHEAD  8
#define DHEAD  64
#define NLAYER 6
#define DFF    2048
#define NTOK   (BATCH*SEQ)

// ---------------- scratch (device globals; no allocation allowed) ----------------
__device__ float g_x    [(size_t)NTOK*DMODEL];         // 16.8 MB  running activations
__device__ float g_qkv  [(size_t)NTOK*3*DMODEL];       // 50.3 MB
__device__ float g_scores[(size_t)BATCH*NHEAD*SEQ*SEQ];// 268 MB
__device__ float g_attno[(size_t)NTOK*DMODEL];         // 16.8 MB
__device__ float g_tmp  [(size_t)NTOK*DMODEL];         // 16.8 MB
__device__ float g_ffn  [(size_t)NTOK*DFF];            // 67.1 MB

// ---------------- positional embedding: cumsum(mask) + sinusoid add ----------------
__global__ void posembed_kernel(const float* __restrict__ xin,
                                const int* __restrict__ mask,
                                float* __restrict__ xout)
{
    int b = blockIdx.x;
    int tid = threadIdx.x;                    // 1024 threads
    __shared__ int sc[SEQ];
    int valid = (mask[b*SEQ + tid] != 0) ? 1 : 0;
    sc[tid] = valid;
    __syncthreads();
    // inclusive Hillis-Steele scan
    for (int off = 1; off < SEQ; off <<= 1) {
        int v = (tid >= off) ? sc[tid - off] : 0;
        __syncthreads();
        sc[tid] += v;
        __syncthreads();
    }
    int pos = sc[tid] * valid;
    __syncthreads();
    sc[tid] = pos;
    __syncthreads();

    const float cfreq = -logf(10000.0f) / 255.0f;   // half-1 = 255
    // cover SEQ*DMODEL elems with 1024 threads, coalesced
    for (int it = 0; it < (SEQ*DMODEL)/SEQ; it++) {
        int idx = it*SEQ + tid;
        int s = idx >> 9;            // /512
        int j = idx & 511;
        int p = sc[s];
        size_t g = ((size_t)b*SEQ + s)*DMODEL + j;
        float add = 0.0f;
        if (p > 0) {
            float fr  = expf((float)(j & 255) * cfreq);
            float ang = (float)p * fr;
            add = (j < 256) ? sinf(ang) : cosf(ang);
        }
        xout[g] = xin[g] + add;
    }
}

// ---------------- generic NN sgemm: C[M,N] = A[M,K] @ B[K,N] (+bias)(+relu) ----------------
// EPI: 0 = none, 1 = +bias, 2 = +bias then relu.  M%128==0, N%128==0, K%16==0.
template<int EPI>
__global__ __launch_bounds__(256) void sgemm_kernel(
    const float* __restrict__ A, const float* __restrict__ B,
    const float* __restrict__ bias, float* __restrict__ C,
    int M, int N, int K)
{
    __shared__ float As[16][128];   // transposed A tile
    __shared__ float Bs[16][128];
    const int bn = blockIdx.x * 128;
    const int bm = blockIdx.y * 128;
    const int tid = threadIdx.x;
    const int tr = tid >> 4;        // 0..15
    const int tc = tid & 15;        // 0..15

    float acc[8][8];
#pragma unroll
    for (int i = 0; i < 8; i++)
#pragma unroll
        for (int j = 0; j < 8; j++) acc[i][j] = 0.0f;

    for (int k0 = 0; k0 < K; k0 += 16) {
#pragma unroll
        for (int i = 0; i < 2; i++) {
            int id = tid + i*256;            // 0..511
            int r  = id >> 2;                // 0..127
            int c4 = (id & 3) * 4;           // 0,4,8,12
            float4 v = *(const float4*)(A + (size_t)(bm + r)*K + k0 + c4);
            As[c4+0][r] = v.x; As[c4+1][r] = v.y; As[c4+2][r] = v.z; As[c4+3][r] = v.w;
        }
#pragma unroll
        for (int i = 0; i < 2; i++) {
            int id = tid + i*256;
            int r  = id >> 5;                // 0..15
            int c4 = (id & 31) * 4;          // 0..124
            *(float4*)&Bs[r][c4] = *(const float4*)(B + (size_t)(k0 + r)*N + bn + c4);
        }
        __syncthreads();
#pragma unroll
        for (int k = 0; k < 16; k++) {
            float a[8], bb[8];
            *(float4*)&a[0]  = *(const float4*)&As[k][tr*8];
            *(float4*)&a[4]  = *(const float4*)&As[k][tr*8 + 4];
            *(float4*)&bb[0] = *(const float4*)&Bs[k][tc*8];
            *(float4*)&bb[4] = *(const float4*)&Bs[k][tc*8 + 4];
#pragma unroll
            for (int i = 0; i < 8; i++)
#pragma unroll
                for (int j = 0; j < 8; j++)
                    acc[i][j] = fmaf(a[i], bb[j], acc[i][j]);
        }
        __syncthreads();
    }

#pragma unroll
    for (int i = 0; i < 8; i++) {
        size_t row = (size_t)(bm + tr*8 + i);
#pragma unroll
        for (int j = 0; j < 8; j += 4) {
            int col = bn + tc*8 + j;
            float4 v = make_float4(acc[i][j], acc[i][j+1], acc[i][j+2], acc[i][j+3]);
            if (EPI >= 1) {
                float4 bv = *(const float4*)(bias + col);
                v.x += bv.x; v.y += bv.y; v.z += bv.z; v.w += bv.w;
            }
            if (EPI == 2) {
                v.x = fmaxf(v.x, 0.0f); v.y = fmaxf(v.y, 0.0f);
                v.z = fmaxf(v.z, 0.0f); v.w = fmaxf(v.w, 0.0f);
            }
            *(float4*)(C + row*N + col) = v;
        }
    }
}

// ---------------- attention: scores = Q @ K^T, masked ----------------
// grid (S/128, S/128, B*H), 256 threads, 128x128 tile, K-dim = 64 in two 32-chunks
__global__ __launch_bounds__(256) void attn_scores_kernel(
    const float* __restrict__ qkv, const int* __restrict__ mask,
    float* __restrict__ scores)
{
    int bh = blockIdx.z;
    int b = bh >> 3, h = bh & 7;
    int q0 = blockIdx.y * 128, k0 = blockIdx.x * 128;
    __shared__ float Qs[32][128];
    __shared__ float Ks[32][128];
    const int tid = threadIdx.x;
    const int tr = tid >> 4, tc = tid & 15;

    float acc[8][8];
#pragma unroll
    for (int i = 0; i < 8; i++)
#pragma unroll
        for (int j = 0; j < 8; j++) acc[i][j] = 0.0f;

    size_t qbase = ((size_t)b*SEQ + q0)*(3*DMODEL) + h*DHEAD;
    size_t kbase = ((size_t)b*SEQ + k0)*(3*DMODEL) + DMODEL + h*DHEAD;

    for (int dc = 0; dc < DHEAD; dc += 32) {
#pragma unroll
        for (int i = 0; i < 4; i++) {
            int id = tid + i*256;            // 0..1023
            int r  = id >> 3;                // 0..127
            int c4 = (id & 7) * 4;           // 0..28
            float4 v = *(const float4*)(qkv + qbase + (size_t)r*(3*DMODEL) + dc + c4);
            Qs[c4+0][r] = v.x; Qs[c4+1][r] = v.y; Qs[c4+2][r] = v.z; Qs[c4+3][r] = v.w;
            float4 w = *(const float4*)(qkv + kbase + (size_t)r*(3*DMODEL) + dc + c4);
            Ks[c4+0][r] = w.x; Ks[c4+1][r] = w.y; Ks[c4+2][r] = w.z; Ks[c4+3][r] = w.w;
        }
        __syncthreads();
#pragma unroll
        for (int k = 0; k < 32; k++) {
            float a[8], bb[8];
            *(float4*)&a[0]  = *(const float4*)&Qs[k][tr*8];
            *(float4*)&a[4]  = *(const float4*)&Qs[k][tr*8 + 4];
            *(float4*)&bb[0] = *(const float4*)&Ks[k][tc*8];
            *(float4*)&bb[4] = *(const float4*)&Ks[k][tc*8 + 4];
#pragma unroll
            for (int i = 0; i < 8; i++)
#pragma unroll
                for (int j = 0; j < 8; j++)
                    acc[i][j] = fmaf(a[i], bb[j], acc[i][j]);
        }
        __syncthreads();
    }

    int km[8];
#pragma unroll
    for (int j = 0; j < 8; j++) km[j] = mask[b*SEQ + k0 + tc*8 + j];

    size_t sbase = (size_t)bh * SEQ * SEQ;
#pragma unroll
    for (int i = 0; i < 8; i++) {
        size_t rb = sbase + (size_t)(q0 + tr*8 + i)*SEQ + k0 + tc*8;
#pragma unroll
        for (int j = 0; j < 8; j += 4) {
            float4 v;
            v.x = km[j+0] ? acc[i][j+0] : -1e30f;
            v.y = km[j+1] ? acc[i][j+1] : -1e30f;
            v.z = km[j+2] ? acc[i][j+2] : -1e30f;
            v.w = km[j+3] ? acc[i][j+3] : -1e30f;
            *(float4*)(scores + rb + j) = v;
        }
    }
}

// ---------------- row softmax over 1024 ----------------
__global__ __launch_bounds__(256) void softmax_kernel(float* __restrict__ p)
{
    size_t base = (size_t)blockIdx.x * SEQ;
    int tid = threadIdx.x;
    __shared__ float red[256];
    float4 v = *(float4*)(p + base + tid*4);
    float mx = fmaxf(fmaxf(v.x, v.y), fmaxf(v.z, v.w));
    red[tid] = mx; __syncthreads();
    for (int off = 128; off; off >>= 1) {
        if (tid < off) red[tid] = fmaxf(red[tid], red[tid + off]);
        __syncthreads();
    }
    mx = red[0]; __syncthreads();
    v.x = expf(v.x - mx); v.y = expf(v.y - mx);
    v.z = expf(v.z - mx); v.w = expf(v.w - mx);
    red[tid] = v.x + v.y + v.z + v.w; __syncthreads();
    for (int off = 128; off; off >>= 1) {
        if (tid < off) red[tid] += red[tid + off];
        __syncthreads();
    }
    float inv = 1.0f / red[0];
    v.x *= inv; v.y *= inv; v.z *= inv; v.w *= inv;
    *(float4*)(p + base + tid*4) = v;
}

// ---------------- O = P @ V, scatter to [B,S,D] layout ----------------
// grid (S/128, B*H), 256 threads, tile 128(q) x 64(d), K=1024 in 32-chunks
__global__ __launch_bounds__(256) void attn_pv_kernel(
    const float* __restrict__ scores, const float* __restrict__ qkv,
    float* __restrict__ out)
{
    int bh = blockIdx.y;
    int b = bh >> 3, h = bh & 7;
    int q0 = blockIdx.x * 128;
    __shared__ float Ps[32][128];
    __shared__ float Vs[32][64];
    const int tid = threadIdx.x;
    const int tr = tid >> 4, tc = tid & 15;

    float acc[8][4];
#pragma unroll
    for (int i = 0; i < 8; i++)
#pragma unroll
        for (int j = 0; j < 4; j++) acc[i][j] = 0.0f;

    size_t pbase = (size_t)bh*SEQ*SEQ + (size_t)q0*SEQ;
    size_t vbase = (size_t)b*SEQ*(3*DMODEL) + 2*DMODEL + h*DHEAD;

    for (int k0 = 0; k0 < SEQ; k0 += 32) {
#pragma unroll
        for (int i = 0; i < 4; i++) {
            int id = tid + i*256;            // 0..1023
            int r  = id >> 3;                // 0..127
            int c4 = (id & 7) * 4;
            float4 v = *(const float4*)(scores + pbase + (size_t)r*SEQ + k0 + c4);
            Ps[c4+0][r] = v.x; Ps[c4+1][r] = v.y; Ps[c4+2][r] = v.z; Ps[c4+3][r] = v.w;
        }
#pragma unroll
        for (int i = 0; i < 2; i++) {
            int id = tid + i*256;            // 0..511
            int r  = id >> 4;                // 0..31
            int c4 = (id & 15) * 4;          // 0..60
            *(float4*)&Vs[r][c4] = *(const float4*)(qkv + vbase + (size_t)(k0 + r)*(3*DMODEL) + c4);
        }
        __syncthreads();
#pragma unroll
        for (int k = 0; k < 32; k++) {
            float a[8];
            *(float4*)&a[0] = *(const float4*)&Ps[k][tr*8];
            *(float4*)&a[4] = *(const float4*)&Ps[k][tr*8 + 4];
            float4 bv = *(const float4*)&Vs[k][tc*4];
#pragma unroll
            for (int i = 0; i < 8; i++) {
                acc[i][0] = fmaf(a[i], bv.x, acc[i][0]);
                acc[i][1] = fmaf(a[i], bv.y, acc[i][1]);
                acc[i][2] = fmaf(a[i], bv.z, acc[i][2]);
                acc[i][3] = fmaf(a[i], bv.w, acc[i][3]);
            }
        }
        __syncthreads();
    }

#pragma unroll
    for (int i = 0; i < 8; i++) {
        size_t o = ((size_t)b*SEQ + q0 + tr*8 + i)*DMODEL + h*DHEAD + tc*4;
        *(float4*)(out + o) = make_float4(acc[i][0], acc[i][1], acc[i][2], acc[i][3]);
    }
}

// ---------------- out = LN(a + r) * g + b ; row length 512 ----------------
__global__ __launch_bounds__(256) void ln_kernel(
    const float* __restrict__ a, const float* __restrict__ r,
    const float* __restrict__ g, const float* __restrict__ be,
    float* __restrict__ out)
{
    int row = blockIdx.x;
    int tid = threadIdx.x;
    __shared__ float red[256];
    size_t base = (size_t)row*DMODEL + tid*2;
    float2 va = *(const float2*)(a + base);
    float2 vr = *(const float2*)(r + base);
    float x0 = va.x + vr.x, x1 = va.y + vr.y;
    red[tid] = x0 + x1; __syncthreads();
    for (int off = 128; off; off >>= 1) {
        if (tid < off) red[tid] += red[tid + off];
        __syncthreads();
    }
    float mu = red[0] * (1.0f/512.0f); __syncthreads();
    float d0 = x0 - mu, d1 = x1 - mu;
    red[tid] = d0*d0 + d1*d1; __syncthreads();
    for (int off = 128; off; off >>= 1) {
        if (tid < off) red[tid] += red[tid + off];
        __syncthreads();
    }
    float inv = rsqrtf(red[0] * (1.0f/512.0f) + 1e-5f);
    float2 gg = *(const float2*)(g + tid*2);
    float2 bb = *(const float2*)(be + tid*2);
    float2 o = make_float2(d0*inv*gg.x + bb.x, d1*inv*gg.y + bb.y);
    *(float2*)(out + base) = o;
}

// ---------------- driver ----------------
extern "C" void kernel_launch(void* const* d_in, const int* in_sizes, int n_in,
                              void* d_out, int out_size)
{
    const float* x_in = (const float*)d_in[0];
    // d_in[1] char_ids (unused), d_in[2] seq_len (unused)
    const int*   mask = (const int*)d_in[3];
    const float* Wqkv = (const float*)d_in[4];
    const float* Wfc  = (const float*)d_in[5];
    const float* bfc  = (const float*)d_in[6];
    const float* ln1g = (const float*)d_in[7];
    const float* ln1b = (const float*)d_in[8];
    const float* ln2g = (const float*)d_in[9];
    const float* ln2b = (const float*)d_in[10];
    const float* W1   = (const float*)d_in[11];
    const float* b1   = (const float*)d_in[12];
    const float* W2   = (const float*)d_in[13];
    const float* b2   = (const float*)d_in[14];

    float *px, *pqkv, *psc, *pao, *ptmp, *pffn;
    cudaGetSymbolAddress((void**)&px,   g_x);
    cudaGetSymbolAddress((void**)&pqkv, g_qkv);
    cudaGetSymbolAddress((void**)&psc,  g_scores);
    cudaGetSymbolAddress((void**)&pao,  g_attno);
    cudaGetSymbolAddress((void**)&ptmp, g_tmp);
    cudaGetSymbolAddress((void**)&pffn, g_ffn);

    posembed_kernel<<<BATCH, SEQ>>>(x_in, mask, px);

    for (int l = 0; l < NLAYER; l++) {
        // QKV projection: [8192,512] @ [512,1536]
        sgemm_kernel<0><<<dim3(3*DMODEL/128, NTOK/128), 256>>>(
            px, Wqkv + (size_t)l*DMODEL*3*DMODEL, nullptr, pqkv, NTOK, 3*DMODEL, DMODEL);
        // scores = Q K^T with key mask
        attn_scores_kernel<<<dim3(SEQ/128, SEQ/128, BATCH*NHEAD), 256>>>(pqkv, mask, psc);
        // softmax rows
        softmax_kernel<<<BATCH*NHEAD*SEQ, 256>>>(psc);
        // O = P V  -> [B,S,D]
        attn_pv_kernel<<<dim3(SEQ/128, BATCH*NHEAD), 256>>>(psc, pqkv, pao);
        // output projection + bias
        sgemm_kernel<1><<<dim3(DMODEL/128, NTOK/128), 256>>>(
            pao, Wfc + (size_t)l*DMODEL*DMODEL, bfc + l*DMODEL, ptmp, NTOK, DMODEL, DMODEL);
        // x = LN(proj + x)
        ln_kernel<<<NTOK, 256>>>(ptmp, px, ln1g + l*DMODEL, ln1b + l*DMODEL, px);
        // FFN up + relu
        sgemm_kernel<2><<<dim3(DFF/128, NTOK/128), 256>>>(
            px, W1 + (size_t)l*DMODEL*DFF, b1 + l*DFF, pffn, NTOK, DFF, DMODEL);
        // FFN down + bias
        sgemm_kernel<1><<<dim3(DMODEL/128, NTOK/128), 256>>>(
            pffn, W2 + (size_t)l*DFF*DMODEL, b2 + l*DMODEL, ptmp, NTOK, DMODEL, DFF);
        // x = LN(h + x)
        ln_kernel<<<NTOK, 256>>>(ptmp, px, ln2g + l*DMODEL, ln2b + l*DMODEL, px);
    }

    cudaMemcpyAsync(d_out, px, (size_t)NTOK*DMODEL*sizeof(float),
                    cudaMemcpyDeviceToDevice);
}

// round 6
// speedup vs baseline: 1.5890x; 1.5890x over previous
#include <cuda_runtime.h>
#include <cuda_bf16.h>
#include <math.h>

#define BATCH  8
#define SEQ    1024
#define DMODEL 512
#define NHEAD  8
#define DHEAD  64
#define NLAYER 6
#define DFF    2048
#define NTOK   (BATCH*SEQ)

// ---- mma.sync GEMM tiling ----
#define TM 128
#define TN 128
#define KC 64
#define PADK 72                       // padded K columns (72*2 = 144B row = 36 banks)
#define MAT_BYTES (128*PADK*2)        // 18432
#define STAGE_BYTES (4*MAT_BYTES)     // Ahi,Alo,Bhi,Blo = 73728
#define GEMM_SMEM (2*STAGE_BYTES)     // 147456

// ---------------- scratch (device globals) ----------------
__device__ float g_x     [(size_t)NTOK*DMODEL];
__device__ __nv_bfloat16 g_xhi[(size_t)NTOK*DMODEL];
__device__ __nv_bfloat16 g_xlo[(size_t)NTOK*DMODEL];
__device__ float g_qkv   [(size_t)NTOK*3*DMODEL];
__device__ float g_scores[(size_t)BATCH*NHEAD*SEQ*SEQ];
__device__ __nv_bfloat16 g_aohi[(size_t)NTOK*DMODEL];
__device__ __nv_bfloat16 g_aolo[(size_t)NTOK*DMODEL];
__device__ float g_tmp   [(size_t)NTOK*DMODEL];
__device__ __nv_bfloat16 g_fhi[(size_t)NTOK*DFF];
__device__ __nv_bfloat16 g_flo[(size_t)NTOK*DFF];
// transposed bf16 hi/lo weights: layout [N, K] per layer
__device__ __nv_bfloat16 g_wqkvhi[(size_t)NLAYER*3*DMODEL*DMODEL];
__device__ __nv_bfloat16 g_wqkvlo[(size_t)NLAYER*3*DMODEL*DMODEL];
__device__ __nv_bfloat16 g_wfchi [(size_t)NLAYER*DMODEL*DMODEL];
__device__ __nv_bfloat16 g_wfclo [(size_t)NLAYER*DMODEL*DMODEL];
__device__ __nv_bfloat16 g_w1hi  [(size_t)NLAYER*DFF*DMODEL];
__device__ __nv_bfloat16 g_w1lo  [(size_t)NLAYER*DFF*DMODEL];
__device__ __nv_bfloat16 g_w2hi  [(size_t)NLAYER*DMODEL*DFF];
__device__ __nv_bfloat16 g_w2lo  [(size_t)NLAYER*DMODEL*DFF];

// ---------------- helpers ----------------
__device__ __forceinline__ unsigned smem_u32(const void* p){
    unsigned a;
    asm("{ .reg .u64 t; cvta.to.shared.u64 t, %1; cvt.u32.u64 %0, t; }":"=r"(a):"l"(p));
    return a;
}
__device__ __forceinline__ void cp16(unsigned saddr, const void* g){
    asm volatile("cp.async.ca.shared.global [%0], [%1], 16;" :: "r"(saddr), "l"(g));
}
#define CP_COMMIT() asm volatile("cp.async.commit_group;" ::: "memory")
template<int N> __device__ __forceinline__ void cp_wait(){
    asm volatile("cp.async.wait_group %0;" :: "n"(N) : "memory");
}
__device__ __forceinline__ void mma16816(float* d, const unsigned* a, const unsigned* b){
    asm volatile(
        "mma.sync.aligned.m16n8k16.row.col.f32.bf16.bf16.f32 "
        "{%0,%1,%2,%3}, {%4,%5,%6,%7}, {%8,%9}, {%0,%1,%2,%3};"
        : "+f"(d[0]), "+f"(d[1]), "+f"(d[2]), "+f"(d[3])
        : "r"(a[0]), "r"(a[1]), "r"(a[2]), "r"(a[3]), "r"(b[0]), "r"(b[1]));
}
__device__ __forceinline__ unsigned ld2bf(const __nv_bfloat16* p){
    return *(const unsigned*)p;
}
__device__ __forceinline__ void split_bf16(float v, __nv_bfloat16& h, __nv_bfloat16& l){
    h = __float2bfloat16(v);
    l = __float2bfloat16(v - __bfloat162float(h));
}

// ---------------- weight prep: W[K,N] fp32 -> T[N,K] bf16 hi/lo ----------------
__global__ void wprep_kernel(const float* __restrict__ W,
                             __nv_bfloat16* __restrict__ Thi,
                             __nv_bfloat16* __restrict__ Tlo,
                             int K, int N)
{
    size_t idx = (size_t)blockIdx.x * 256 + threadIdx.x;
    if (idx >= (size_t)K * N) return;
    int n = (int)(idx / K);
    int k = (int)(idx - (size_t)n * K);
    float v = W[(size_t)k * N + n];
    __nv_bfloat16 h, l; split_bf16(v, h, l);
    Thi[idx] = h; Tlo[idx] = l;
}

// ---------------- mma.sync split-bf16 GEMM ----------------
// C[M,N] = A[M,K] @ B^T ; A as hi/lo [M,K], B as hi/lo [N,K].
// EPI: 0 -> fp32 store; 1 -> +bias fp32 store; 2 -> +bias, relu, bf16-pair store.
template<int EPI>
__global__ __launch_bounds__(256, 1) void mma_gemm_kernel(
    const __nv_bfloat16* __restrict__ Ahi, const __nv_bfloat16* __restrict__ Alo,
    const __nv_bfloat16* __restrict__ Bhi, const __nv_bfloat16* __restrict__ Blo,
    const float* __restrict__ bias,
    float* __restrict__ Cf,
    __nv_bfloat16* __restrict__ Chi, __nv_bfloat16* __restrict__ Clo,
    int N, int K)
{
    extern __shared__ char smem[];
    const unsigned sbase = smem_u32(smem);
    const int tid = threadIdx.x;
    const int wid = tid >> 5, lane = tid & 31;
    const int wr = wid & 3;           // warp row 0..3  (32 rows each)
    const int wc = wid >> 2;          // warp col 0..1  (64 cols each)
    const int bm = blockIdx.y * TM;
    const int bn = blockIdx.x * TN;

    // per-thread load coords: 1024 16B-vectors per 128x64 matrix, 4 per thread
    const int lr = tid >> 3;          // base row (stride 32 over 4 iters)
    const int lg = tid & 7;           // 16B group within row

    float acc[2][8][4];
#pragma unroll
    for (int ma = 0; ma < 2; ma++)
#pragma unroll
        for (int na = 0; na < 8; na++)
#pragma unroll
            for (int j = 0; j < 4; j++) acc[ma][na][j] = 0.0f;

    const int NC = K >> 6;

    // ---- prefetch chunk 0 into stage 0 ----
    {
        const unsigned st = sbase;
#pragma unroll
        for (int i = 0; i < 4; i++) {
            int r = lr + i*32;
            unsigned so = (unsigned)(r*144 + lg*16);
            size_t ga = (size_t)(bm + r)*K + lg*8;
            size_t gb = (size_t)(bn + r)*K + lg*8;
            cp16(st + so,                 Ahi + ga);
            cp16(st + MAT_BYTES + so,     Alo + ga);
            cp16(st + 2*MAT_BYTES + so,   Bhi + gb);
            cp16(st + 3*MAT_BYTES + so,   Blo + gb);
        }
        CP_COMMIT();
    }

    for (int c = 0; c < NC; c++) {
        if (c + 1 < NC) {
            const unsigned st = sbase + ((c+1) & 1)*STAGE_BYTES;
            const int k0 = (c+1)*KC;
#pragma unroll
            for (int i = 0; i < 4; i++) {
                int r = lr + i*32;
                unsigned so = (unsigned)(r*144 + lg*16);
                size_t ga = (size_t)(bm + r)*K + k0 + lg*8;
                size_t gb = (size_t)(bn + r)*K + k0 + lg*8;
                cp16(st + so,                 Ahi + ga);
                cp16(st + MAT_BYTES + so,     Alo + ga);
                cp16(st + 2*MAT_BYTES + so,   Bhi + gb);
                cp16(st + 3*MAT_BYTES + so,   Blo + gb);
            }
            CP_COMMIT();
            cp_wait<1>();
        } else {
            cp_wait<0>();
        }
        __syncthreads();

        const char* stg = smem + (c & 1)*STAGE_BYTES;
        const __nv_bfloat16* sAh = (const __nv_bfloat16*)(stg);
        const __nv_bfloat16* sAl = (const __nv_bfloat16*)(stg + MAT_BYTES);
        const __nv_bfloat16* sBh = (const __nv_bfloat16*)(stg + 2*MAT_BYTES);
        const __nv_bfloat16* sBl = (const __nv_bfloat16*)(stg + 3*MAT_BYTES);

#pragma unroll
        for (int ks = 0; ks < 4; ks++) {
            const int kk = ks*16 + (lane & 3)*2;
            unsigned ah[2][4], al[2][4];
#pragma unroll
            for (int ma = 0; ma < 2; ma++) {
                const int r0 = wr*32 + ma*16 + (lane >> 2);
                ah[ma][0] = ld2bf(sAh + r0*PADK + kk);
                ah[ma][1] = ld2bf(sAh + (r0+8)*PADK + kk);
                ah[ma][2] = ld2bf(sAh + r0*PADK + kk + 8);
                ah[ma][3] = ld2bf(sAh + (r0+8)*PADK + kk + 8);
                al[ma][0] = ld2bf(sAl + r0*PADK + kk);
                al[ma][1] = ld2bf(sAl + (r0+8)*PADK + kk);
                al[ma][2] = ld2bf(sAl + r0*PADK + kk + 8);
                al[ma][3] = ld2bf(sAl + (r0+8)*PADK + kk + 8);
            }
            unsigned bh[8][2], bl[8][2];
#pragma unroll
            for (int na = 0; na < 8; na++) {
                const int n0 = wc*64 + na*8 + (lane >> 2);
                bh[na][0] = ld2bf(sBh + n0*PADK + kk);
                bh[na][1] = ld2bf(sBh + n0*PADK + kk + 8);
                bl[na][0] = ld2bf(sBl + n0*PADK + kk);
                bl[na][1] = ld2bf(sBl + n0*PADK + kk + 8);
            }
            // product 1: Ahi * Bhi
#pragma unroll
            for (int ma = 0; ma < 2; ma++)
#pragma unroll
                for (int na = 0; na < 8; na++)
                    mma16816(acc[ma][na], ah[ma], bh[na]);
            // product 2: Ahi * Blo
#pragma unroll
            for (int ma = 0; ma < 2; ma++)
#pragma unroll
                for (int na = 0; na < 8; na++)
                    mma16816(acc[ma][na], ah[ma], bl[na]);
            // product 3: Alo * Bhi
#pragma unroll
            for (int ma = 0; ma < 2; ma++)
#pragma unroll
                for (int na = 0; na < 8; na++)
                    mma16816(acc[ma][na], al[ma], bh[na]);
        }
        __syncthreads();
    }

    // ---- epilogue ----
#pragma unroll
    for (int ma = 0; ma < 2; ma++) {
        const int r0 = bm + wr*32 + ma*16 + (lane >> 2);
#pragma unroll
        for (int na = 0; na < 8; na++) {
            const int cc = bn + wc*64 + na*8 + (lane & 3)*2;
            float v0 = acc[ma][na][0], v1 = acc[ma][na][1];
            float v2 = acc[ma][na][2], v3 = acc[ma][na][3];
            if (EPI >= 1) {
                float2 bv = *(const float2*)(bias + cc);
                v0 += bv.x; v1 += bv.y; v2 += bv.x; v3 += bv.y;
            }
            if (EPI == 2) {
                v0 = fmaxf(v0, 0.0f); v1 = fmaxf(v1, 0.0f);
                v2 = fmaxf(v2, 0.0f); v3 = fmaxf(v3, 0.0f);
                __nv_bfloat16 h0,l0,h1,l1;
                split_bf16(v0,h0,l0); split_bf16(v1,h1,l1);
                __nv_bfloat162 hp, lp;
                hp.x=h0; hp.y=h1; lp.x=l0; lp.y=l1;
                *(__nv_bfloat162*)(Chi + (size_t)r0*N + cc) = hp;
                *(__nv_bfloat162*)(Clo + (size_t)r0*N + cc) = lp;
                split_bf16(v2,h0,l0); split_bf16(v3,h1,l1);
                hp.x=h0; hp.y=h1; lp.x=l0; lp.y=l1;
                *(__nv_bfloat162*)(Chi + (size_t)(r0+8)*N + cc) = hp;
                *(__nv_bfloat162*)(Clo + (size_t)(r0+8)*N + cc) = lp;
            } else {
                *(float2*)(Cf + (size_t)r0*N + cc)     = make_float2(v0, v1);
                *(float2*)(Cf + (size_t)(r0+8)*N + cc) = make_float2(v2, v3);
            }
        }
    }
}

// ---------------- positional embedding + pair split ----------------
__global__ void posembed_kernel(const float* __restrict__ xin,
                                const int* __restrict__ mask,
                                float* __restrict__ xout,
                                __nv_bfloat16* __restrict__ xhi,
                                __nv_bfloat16* __restrict__ xlo)
{
    int b = blockIdx.x;
    int tid = threadIdx.x;                    // 1024 threads
    __shared__ int sc[SEQ];
    int valid = (mask[b*SEQ + tid] != 0) ? 1 : 0;
    sc[tid] = valid;
    __syncthreads();
    for (int off = 1; off < SEQ; off <<= 1) {
        int v = (tid >= off) ? sc[tid - off] : 0;
        __syncthreads();
        sc[tid] += v;
        __syncthreads();
    }
    int pos = sc[tid] * valid;
    __syncthreads();
    sc[tid] = pos;
    __syncthreads();

    const float cfreq = -logf(10000.0f) / 255.0f;
    for (int it = 0; it < (SEQ*DMODEL)/SEQ; it++) {
        int idx = it*SEQ + tid;
        int s = idx >> 9;
        int j = idx & 511;
        int p = sc[s];
        size_t g = ((size_t)b*SEQ + s)*DMODEL + j;
        float add = 0.0f;
        if (p > 0) {
            float fr  = expf((float)(j & 255) * cfreq);
            float ang = (float)p * fr;
            add = (j < 256) ? sinf(ang) : cosf(ang);
        }
        float v = xin[g] + add;
        xout[g] = v;
        __nv_bfloat16 h, l; split_bf16(v, h, l);
        xhi[g] = h; xlo[g] = l;
    }
}

// ---------------- attention: scores = Q @ K^T, masked ----------------
__global__ __launch_bounds__(256) void attn_scores_kernel(
    const float* __restrict__ qkv, const int* __restrict__ mask,
    float* __restrict__ scores)
{
    int bh = blockIdx.z;
    int b = bh >> 3, h = bh & 7;
    int q0 = blockIdx.y * 128, k0 = blockIdx.x * 128;
    __shared__ float Qs[32][128];
    __shared__ float Ks[32][128];
    const int tid = threadIdx.x;
    const int tr = tid >> 4, tc = tid & 15;

    float acc[8][8];
#pragma unroll
    for (int i = 0; i < 8; i++)
#pragma unroll
        for (int j = 0; j < 8; j++) acc[i][j] = 0.0f;

    size_t qbase = ((size_t)b*SEQ + q0)*(3*DMODEL) + h*DHEAD;
    size_t kbase = ((size_t)b*SEQ + k0)*(3*DMODEL) + DMODEL + h*DHEAD;

    for (int dc = 0; dc < DHEAD; dc += 32) {
#pragma unroll
        for (int i = 0; i < 4; i++) {
            int id = tid + i*256;
            int r  = id >> 3;
            int c4 = (id & 7) * 4;
            float4 v = *(const float4*)(qkv + qbase + (size_t)r*(3*DMODEL) + dc + c4);
            Qs[c4+0][r] = v.x; Qs[c4+1][r] = v.y; Qs[c4+2][r] = v.z; Qs[c4+3][r] = v.w;
            float4 w = *(const float4*)(qkv + kbase + (size_t)r*(3*DMODEL) + dc + c4);
            Ks[c4+0][r] = w.x; Ks[c4+1][r] = w.y; Ks[c4+2][r] = w.z; Ks[c4+3][r] = w.w;
        }
        __syncthreads();
#pragma unroll
        for (int k = 0; k < 32; k++) {
            float a[8], bb[8];
            *(float4*)&a[0]  = *(const float4*)&Qs[k][tr*8];
            *(float4*)&a[4]  = *(const float4*)&Qs[k][tr*8 + 4];
            *(float4*)&bb[0] = *(const float4*)&Ks[k][tc*8];
            *(float4*)&bb[4] = *(const float4*)&Ks[k][tc*8 + 4];
#pragma unroll
            for (int i = 0; i < 8; i++)
#pragma unroll
                for (int j = 0; j < 8; j++)
                    acc[i][j] = fmaf(a[i], bb[j], acc[i][j]);
        }
        __syncthreads();
    }

    int km[8];
#pragma unroll
    for (int j = 0; j < 8; j++) km[j] = mask[b*SEQ + k0 + tc*8 + j];

    size_t sbase = (size_t)bh * SEQ * SEQ;
#pragma unroll
    for (int i = 0; i < 8; i++) {
        size_t rb = sbase + (size_t)(q0 + tr*8 + i)*SEQ + k0 + tc*8;
#pragma unroll
        for (int j = 0; j < 8; j += 4) {
            float4 v;
            v.x = km[j+0] ? acc[i][j+0] : -1e30f;
            v.y = km[j+1] ? acc[i][j+1] : -1e30f;
            v.z = km[j+2] ? acc[i][j+2] : -1e30f;
            v.w = km[j+3] ? acc[i][j+3] : -1e30f;
            *(float4*)(scores + rb + j) = v;
        }
    }
}

// ---------------- row softmax over 1024 ----------------
__global__ __launch_bounds__(256) void softmax_kernel(float* __restrict__ p)
{
    size_t base = (size_t)blockIdx.x * SEQ;
    int tid = threadIdx.x;
    __shared__ float red[256];
    float4 v = *(float4*)(p + base + tid*4);
    float mx = fmaxf(fmaxf(v.x, v.y), fmaxf(v.z, v.w));
    red[tid] = mx; __syncthreads();
    for (int off = 128; off; off >>= 1) {
        if (tid < off) red[tid] = fmaxf(red[tid], red[tid + off]);
        __syncthreads();
    }
    mx = red[0]; __syncthreads();
    v.x = expf(v.x - mx); v.y = expf(v.y - mx);
    v.z = expf(v.z - mx); v.w = expf(v.w - mx);
    red[tid] = v.x + v.y + v.z + v.w; __syncthreads();
    for (int off = 128; off; off >>= 1) {
        if (tid < off) red[tid] += red[tid + off];
        __syncthreads();
    }
    float inv = 1.0f / red[0];
    v.x *= inv; v.y *= inv; v.z *= inv; v.w *= inv;
    *(float4*)(p + base + tid*4) = v;
}

// ---------------- O = P @ V, scatter to [B,S,D] layout as bf16 hi/lo pair ----------------
__global__ __launch_bounds__(256) void attn_pv_kernel(
    const float* __restrict__ scores, const float* __restrict__ qkv,
    __nv_bfloat16* __restrict__ ohi, __nv_bfloat16* __restrict__ olo)
{
    int bh = blockIdx.y;
    int b = bh >> 3, h = bh & 7;
    int q0 = blockIdx.x * 128;
    __shared__ float Ps[32][128];
    __shared__ float Vs[32][64];
    const int tid = threadIdx.x;
    const int tr = tid >> 4, tc = tid & 15;

    float acc[8][4];
#pragma unroll
    for (int i = 0; i < 8; i++)
#pragma unroll
        for (int j = 0; j < 4; j++) acc[i][j] = 0.0f;

    size_t pbase = (size_t)bh*SEQ*SEQ + (size_t)q0*SEQ;
    size_t vbase = (size_t)b*SEQ*(3*DMODEL) + 2*DMODEL + h*DHEAD;

    for (int k0 = 0; k0 < SEQ; k0 += 32) {
#pragma unroll
        for (int i = 0; i < 4; i++) {
            int id = tid + i*256;
            int r  = id >> 3;
            int c4 = (id & 7) * 4;
            float4 v = *(const float4*)(scores + pbase + (size_t)r*SEQ + k0 + c4);
            Ps[c4+0][r] = v.x; Ps[c4+1][r] = v.y; Ps[c4+2][r] = v.z; Ps[c4+3][r] = v.w;
        }
#pragma unroll
        for (int i = 0; i < 2; i++) {
            int id = tid + i*256;
            int r  = id >> 4;
            int c4 = (id & 15) * 4;
            *(float4*)&Vs[r][c4] = *(const float4*)(qkv + vbase + (size_t)(k0 + r)*(3*DMODEL) + c4);
        }
        __syncthreads();
#pragma unroll
        for (int k = 0; k < 32; k++) {
            float a[8];
            *(float4*)&a[0] = *(const float4*)&Ps[k][tr*8];
            *(float4*)&a[4] = *(const float4*)&Ps[k][tr*8 + 4];
            float4 bv = *(const float4*)&Vs[k][tc*4];
#pragma unroll
            for (int i = 0; i < 8; i++) {
                acc[i][0] = fmaf(a[i], bv.x, acc[i][0]);
                acc[i][1] = fmaf(a[i], bv.y, acc[i][1]);
                acc[i][2] = fmaf(a[i], bv.z, acc[i][2]);
                acc[i][3] = fmaf(a[i], bv.w, acc[i][3]);
            }
        }
        __syncthreads();
    }

#pragma unroll
    for (int i = 0; i < 8; i++) {
        size_t o = ((size_t)b*SEQ + q0 + tr*8 + i)*DMODEL + h*DHEAD + tc*4;
#pragma unroll
        for (int j = 0; j < 4; j += 2) {
            __nv_bfloat16 h0, l0, h1, l1;
            split_bf16(acc[i][j],   h0, l0);
            split_bf16(acc[i][j+1], h1, l1);
            __nv_bfloat162 hp; hp.x = h0; hp.y = h1;
            __nv_bfloat162 lp; lp.x = l0; lp.y = l1;
            *(__nv_bfloat162*)(ohi + o + j) = hp;
            *(__nv_bfloat162*)(olo + o + j) = lp;
        }
    }
}

// ---------------- out = LN(a + r) * g + b ; also emits bf16 pair ----------------
__global__ __launch_bounds__(256) void ln_kernel(
    const float* __restrict__ a, const float* __restrict__ r,
    const float* __restrict__ g, const float* __restrict__ be,
    float* __restrict__ out,
    __nv_bfloat16* __restrict__ ohi, __nv_bfloat16* __restrict__ olo)
{
    int row = blockIdx.x;
    int tid = threadIdx.x;
    __shared__ float red[256];
    size_t base = (size_t)row*DMODEL + tid*2;
    float2 va = *(const float2*)(a + base);
    float2 vr = *(const float2*)(r + base);
    float x0 = va.x + vr.x, x1 = va.y + vr.y;
    red[tid] = x0 + x1; __syncthreads();
    for (int off = 128; off; off >>= 1) {
        if (tid < off) red[tid] += red[tid + off];
        __syncthreads();
    }
    float mu = red[0] * (1.0f/512.0f); __syncthreads();
    float d0 = x0 - mu, d1 = x1 - mu;
    red[tid] = d0*d0 + d1*d1; __syncthreads();
    for (int off = 128; off; off >>= 1) {
        if (tid < off) red[tid] += red[tid + off];
        __syncthreads();
    }
    float inv = rsqrtf(red[0] * (1.0f/512.0f) + 1e-5f);
    float2 gg = *(const float2*)(g + tid*2);
    float2 bb = *(const float2*)(be + tid*2);
    float o0 = d0*inv*gg.x + bb.x;
    float o1 = d1*inv*gg.y + bb.y;
    *(float2*)(out + base) = make_float2(o0, o1);
    __nv_bfloat16 h0, l0, h1, l1;
    split_bf16(o0, h0, l0); split_bf16(o1, h1, l1);
    __nv_bfloat162 hp; hp.x = h0; hp.y = h1;
    __nv_bfloat162 lp; lp.x = l0; lp.y = l1;
    *(__nv_bfloat162*)(ohi + base) = hp;
    *(__nv_bfloat162*)(olo + base) = lp;
}

// ---------------- driver ----------------
extern "C" void kernel_launch(void* const* d_in, const int* in_sizes, int n_in,
                              void* d_out, int out_size)
{
    const float* x_in = (const float*)d_in[0];
    const int*   mask = (const int*)d_in[3];
    const float* Wqkv = (const float*)d_in[4];
    const float* Wfc  = (const float*)d_in[5];
    const float* bfc  = (const float*)d_in[6];
    const float* ln1g = (const float*)d_in[7];
    const float* ln1b = (const float*)d_in[8];
    const float* ln2g = (const float*)d_in[9];
    const float* ln2b = (const float*)d_in[10];
    const float* W1   = (const float*)d_in[11];
    const float* b1   = (const float*)d_in[12];
    const float* W2   = (const float*)d_in[13];
    const float* b2   = (const float*)d_in[14];

    float *px, *pqkv, *psc, *ptmp;
    __nv_bfloat16 *pxhi, *pxlo, *paohi, *paolo, *pfhi, *pflo;
    __nv_bfloat16 *wqh, *wql, *wfh, *wfl, *w1h, *w1l, *w2h, *w2l;
    cudaGetSymbolAddress((void**)&px,    g_x);
    cudaGetSymbolAddress((void**)&pxhi,  g_xhi);
    cudaGetSymbolAddress((void**)&pxlo,  g_xlo);
    cudaGetSymbolAddress((void**)&pqkv,  g_qkv);
    cudaGetSymbolAddress((void**)&psc,   g_scores);
    cudaGetSymbolAddress((void**)&paohi, g_aohi);
    cudaGetSymbolAddress((void**)&paolo, g_aolo);
    cudaGetSymbolAddress((void**)&ptmp,  g_tmp);
    cudaGetSymbolAddress((void**)&pfhi,  g_fhi);
    cudaGetSymbolAddress((void**)&pflo,  g_flo);
    cudaGetSymbolAddress((void**)&wqh,   g_wqkvhi);
    cudaGetSymbolAddress((void**)&wql,   g_wqkvlo);
    cudaGetSymbolAddress((void**)&wfh,   g_wfchi);
    cudaGetSymbolAddress((void**)&wfl,   g_wfclo);
    cudaGetSymbolAddress((void**)&w1h,   g_w1hi);
    cudaGetSymbolAddress((void**)&w1l,   g_w1lo);
    cudaGetSymbolAddress((void**)&w2h,   g_w2hi);
    cudaGetSymbolAddress((void**)&w2l,   g_w2lo);

    cudaFuncSetAttribute(mma_gemm_kernel<0>, cudaFuncAttributeMaxDynamicSharedMemorySize, GEMM_SMEM);
    cudaFuncSetAttribute(mma_gemm_kernel<1>, cudaFuncAttributeMaxDynamicSharedMemorySize, GEMM_SMEM);
    cudaFuncSetAttribute(mma_gemm_kernel<2>, cudaFuncAttributeMaxDynamicSharedMemorySize, GEMM_SMEM);

    // weight prep (transpose + split), per layer
    for (int l = 0; l < NLAYER; l++) {
        size_t oq = (size_t)l*3*DMODEL*DMODEL;
        size_t of = (size_t)l*DMODEL*DMODEL;
        size_t o1 = (size_t)l*DFF*DMODEL;
        size_t o2 = (size_t)l*DMODEL*DFF;
        wprep_kernel<<<(3*DMODEL*DMODEL + 255)/256, 256>>>(Wqkv + oq, wqh + oq, wql + oq, DMODEL, 3*DMODEL);
        wprep_kernel<<<(DMODEL*DMODEL + 255)/256, 256>>>(Wfc + of, wfh + of, wfl + of, DMODEL, DMODEL);
        wprep_kernel<<<(DFF*DMODEL + 255)/256, 256>>>(W1 + o1, w1h + o1, w1l + o1, DMODEL, DFF);
        wprep_kernel<<<(DMODEL*DFF + 255)/256, 256>>>(W2 + o2, w2h + o2, w2l + o2, DFF, DMODEL);
    }

    posembed_kernel<<<BATCH, SEQ>>>(x_in, mask, px, pxhi, pxlo);

    for (int l = 0; l < NLAYER; l++) {
        size_t oq = (size_t)l*3*DMODEL*DMODEL;
        size_t of = (size_t)l*DMODEL*DMODEL;
        size_t o1 = (size_t)l*DFF*DMODEL;
        size_t o2 = (size_t)l*DMODEL*DFF;
        // QKV: [8192,512] x [1536,512]^T  (no bias) -> fp32 qkv
        mma_gemm_kernel<0><<<dim3(3*DMODEL/TN, NTOK/TM), 256, GEMM_SMEM>>>(
            pxhi, pxlo, wqh + oq, wql + oq, nullptr, pqkv, nullptr, nullptr, 3*DMODEL, DMODEL);
        attn_scores_kernel<<<dim3(SEQ/128, SEQ/128, BATCH*NHEAD), 256>>>(pqkv, mask, psc);
        softmax_kernel<<<BATCH*NHEAD*SEQ, 256>>>(psc);
        attn_pv_kernel<<<dim3(SEQ/128, BATCH*NHEAD), 256>>>(psc, pqkv, paohi, paolo);
        // proj + bias -> fp32
        mma_gemm_kernel<1><<<dim3(DMODEL/TN, NTOK/TM), 256, GEMM_SMEM>>>(
            paohi, paolo, wfh + of, wfl + of, bfc + l*DMODEL, ptmp, nullptr, nullptr, DMODEL, DMODEL);
        ln_kernel<<<NTOK, 256>>>(ptmp, px, ln1g + l*DMODEL, ln1b + l*DMODEL, px, pxhi, pxlo);
        // FFN up + relu -> bf16 pair
        mma_gemm_kernel<2><<<dim3(DFF/TN, NTOK/TM), 256, GEMM_SMEM>>>(
            pxhi, pxlo, w1h + o1, w1l + o1, b1 + l*DFF, nullptr, pfhi, pflo, DFF, DMODEL);
        // FFN down + bias -> fp32
        mma_gemm_kernel<1><<<dim3(DMODEL/TN, NTOK/TM), 256, GEMM_SMEM>>>(
            pfhi, pflo, w2h + o2, w2l + o2, b2 + l*DMODEL, ptmp, nullptr, nullptr, DMODEL, DFF);
        ln_kernel<<<NTOK, 256>>>(ptmp, px, ln2g + l*DMODEL, ln2b + l*DMODEL, px, pxhi, pxlo);
    }

    cudaMemcpyAsync(d_out, px, (size_t)NTOK*DMODEL*sizeof(float),
                    cudaMemcpyDeviceToDevice);
}

// round 7
// speedup vs baseline: 2.5934x; 1.6321x over previous
#include <cuda_runtime.h>
#include <cuda_bf16.h>
#include <math.h>

#define BATCH  8
#define SEQ    1024
#define DMODEL 512
#define NHEAD  8
#define DHEAD  64
#define NLAYER 6
#define DFF    2048
#define NTOK   (BATCH*SEQ)

// ---- mma.sync GEMM tiling ----
#define TM 128
#define TN 128
#define KC 64
#define PADK 72                       // padded K columns (72*2 = 144B row = 36 banks)
#define MAT_BYTES (128*PADK*2)        // 18432
#define STAGE_BYTES (4*MAT_BYTES)     // Ahi,Alo,Bhi,Blo = 73728
#define GEMM_SMEM (2*STAGE_BYTES)     // 147456

// ---- flash attention tiling ----
#define FPAD 72
#define NTILE 16
// bf16-element offsets in dynamic smem
#define Q_HI 0
#define Q_LO 9216
#define FSTG(s) (18432 + (s)*18560)
#define KS_HI(s) (FSTG(s))
#define KS_LO(s) (FSTG(s)+4608)
#define VS_HI(s) (FSTG(s)+9216)
#define VS_LO(s) (FSTG(s)+13824)
#define BI_F(s)  (FSTG(s)+18432)      // 64 floats = 128 bf16 elems
#define FLASH_SMEM (2*(18432 + 2*18560))   // 111104 bytes

// ---------------- scratch (device globals) ----------------
__device__ float g_x     [(size_t)NTOK*DMODEL];
__device__ __nv_bfloat16 g_xhi[(size_t)NTOK*DMODEL];
__device__ __nv_bfloat16 g_xlo[(size_t)NTOK*DMODEL];
__device__ __nv_bfloat16 g_qkvhi[(size_t)NTOK*3*DMODEL];
__device__ __nv_bfloat16 g_qkvlo[(size_t)NTOK*3*DMODEL];
__device__ __nv_bfloat16 g_vthi[(size_t)BATCH*NHEAD*DHEAD*SEQ];
__device__ __nv_bfloat16 g_vtlo[(size_t)BATCH*NHEAD*DHEAD*SEQ];
__device__ float g_kbias [(size_t)BATCH*SEQ];
__device__ __nv_bfloat16 g_aohi[(size_t)NTOK*DMODEL];
__device__ __nv_bfloat16 g_aolo[(size_t)NTOK*DMODEL];
__device__ float g_tmp   [(size_t)NTOK*DMODEL];
__device__ __nv_bfloat16 g_fhi[(size_t)NTOK*DFF];
__device__ __nv_bfloat16 g_flo[(size_t)NTOK*DFF];
// transposed bf16 hi/lo weights: layout [N, K] per layer
__device__ __nv_bfloat16 g_wqkvhi[(size_t)NLAYER*3*DMODEL*DMODEL];
__device__ __nv_bfloat16 g_wqkvlo[(size_t)NLAYER*3*DMODEL*DMODEL];
__device__ __nv_bfloat16 g_wfchi [(size_t)NLAYER*DMODEL*DMODEL];
__device__ __nv_bfloat16 g_wfclo [(size_t)NLAYER*DMODEL*DMODEL];
__device__ __nv_bfloat16 g_w1hi  [(size_t)NLAYER*DFF*DMODEL];
__device__ __nv_bfloat16 g_w1lo  [(size_t)NLAYER*DFF*DMODEL];
__device__ __nv_bfloat16 g_w2hi  [(size_t)NLAYER*DMODEL*DFF];
__device__ __nv_bfloat16 g_w2lo  [(size_t)NLAYER*DMODEL*DFF];

// ---------------- helpers ----------------
__device__ __forceinline__ unsigned smem_u32(const void* p){
    unsigned a;
    asm("{ .reg .u64 t; cvta.to.shared.u64 t, %1; cvt.u32.u64 %0, t; }":"=r"(a):"l"(p));
    return a;
}
__device__ __forceinline__ void cp16(unsigned saddr, const void* g){
    asm volatile("cp.async.ca.shared.global [%0], [%1], 16;" :: "r"(saddr), "l"(g));
}
#define CP_COMMIT() asm volatile("cp.async.commit_group;" ::: "memory")
template<int N> __device__ __forceinline__ void cp_wait(){
    asm volatile("cp.async.wait_group %0;" :: "n"(N) : "memory");
}
__device__ __forceinline__ void mma16816(float* d, const unsigned* a, const unsigned* b){
    asm volatile(
        "mma.sync.aligned.m16n8k16.row.col.f32.bf16.bf16.f32 "
        "{%0,%1,%2,%3}, {%4,%5,%6,%7}, {%8,%9}, {%0,%1,%2,%3};"
        : "+f"(d[0]), "+f"(d[1]), "+f"(d[2]), "+f"(d[3])
        : "r"(a[0]), "r"(a[1]), "r"(a[2]), "r"(a[3]), "r"(b[0]), "r"(b[1]));
}
__device__ __forceinline__ unsigned ld2bf(const __nv_bfloat16* p){
    return *(const unsigned*)p;
}
__device__ __forceinline__ void split_bf16(float v, __nv_bfloat16& h, __nv_bfloat16& l){
    h = __float2bfloat16(v);
    l = __float2bfloat16(v - __bfloat162float(h));
}
// split two floats into packed bf16x2 hi and lo words
__device__ __forceinline__ void split2(float a, float b, unsigned& hi, unsigned& lo){
    __nv_bfloat16 ha = __float2bfloat16(a), hb = __float2bfloat16(b);
    __nv_bfloat162 hp; hp.x = ha; hp.y = hb;
    __nv_bfloat162 lp;
    lp.x = __float2bfloat16(a - __bfloat162float(ha));
    lp.y = __float2bfloat16(b - __bfloat162float(hb));
    hi = *(unsigned*)&hp; lo = *(unsigned*)&lp;
}

// ---------------- weight prep: W[L][K][N] fp32 -> T[L][N][K] bf16 hi/lo (tiled transpose) ----------------
__global__ __launch_bounds__(256) void wprep_kernel(const float* __restrict__ W,
                             __nv_bfloat16* __restrict__ Thi,
                             __nv_bfloat16* __restrict__ Tlo,
                             int K, int N)
{
    __shared__ float tf[32][33];
    const int l = blockIdx.z;
    const int n0 = blockIdx.x*32, k0 = blockIdx.y*32;
    const int tx = threadIdx.x & 31, ty = threadIdx.x >> 5;
    const float* Wl = W + (size_t)l*K*N;
#pragma unroll
    for (int i = 0; i < 4; i++) {
        int k = k0 + ty*4 + i;
        tf[ty*4+i][tx] = Wl[(size_t)k*N + n0 + tx];
    }
    __syncthreads();
    __nv_bfloat16* Th = Thi + (size_t)l*K*N;
    __nv_bfloat16* Tl = Tlo + (size_t)l*K*N;
#pragma unroll
    for (int i = 0; i < 4; i++) {
        int n = n0 + ty*4 + i;
        float v = tf[tx][ty*4+i];
        __nv_bfloat16 h, lo; split_bf16(v, h, lo);
        Th[(size_t)n*K + k0 + tx] = h;
        Tl[(size_t)n*K + k0 + tx] = lo;
    }
}

// ---------------- mma.sync split-bf16 GEMM ----------------
// C[M,N] = A[M,K] @ B^T ; A as hi/lo [M,K], B as hi/lo [N,K].
// EPI: 0 fp32; 1 +bias fp32; 2 +bias+relu bf16-pair; 3 bf16-pair (no bias).
template<int EPI>
__global__ __launch_bounds__(256, 1) void mma_gemm_kernel(
    const __nv_bfloat16* __restrict__ Ahi, const __nv_bfloat16* __restrict__ Alo,
    const __nv_bfloat16* __restrict__ Bhi, const __nv_bfloat16* __restrict__ Blo,
    const float* __restrict__ bias,
    float* __restrict__ Cf,
    __nv_bfloat16* __restrict__ Chi, __nv_bfloat16* __restrict__ Clo,
    int N, int K)
{
    extern __shared__ char smem[];
    const unsigned sbase = smem_u32(smem);
    const int tid = threadIdx.x;
    const int wid = tid >> 5, lane = tid & 31;
    const int wr = wid & 3;
    const int wc = wid >> 2;
    const int bm = blockIdx.y * TM;
    const int bn = blockIdx.x * TN;

    const int lr = tid >> 3;
    const int lg = tid & 7;

    float acc[2][8][4];
#pragma unroll
    for (int ma = 0; ma < 2; ma++)
#pragma unroll
        for (int na = 0; na < 8; na++)
#pragma unroll
            for (int j = 0; j < 4; j++) acc[ma][na][j] = 0.0f;

    const int NC = K >> 6;

    {
        const unsigned st = sbase;
#pragma unroll
        for (int i = 0; i < 4; i++) {
            int r = lr + i*32;
            unsigned so = (unsigned)(r*144 + lg*16);
            size_t ga = (size_t)(bm + r)*K + lg*8;
            size_t gb = (size_t)(bn + r)*K + lg*8;
            cp16(st + so,                 Ahi + ga);
            cp16(st + MAT_BYTES + so,     Alo + ga);
            cp16(st + 2*MAT_BYTES + so,   Bhi + gb);
            cp16(st + 3*MAT_BYTES + so,   Blo + gb);
        }
        CP_COMMIT();
    }

    for (int c = 0; c < NC; c++) {
        if (c + 1 < NC) {
            const unsigned st = sbase + ((c+1) & 1)*STAGE_BYTES;
            const int k0 = (c+1)*KC;
#pragma unroll
            for (int i = 0; i < 4; i++) {
                int r = lr + i*32;
                unsigned so = (unsigned)(r*144 + lg*16);
                size_t ga = (size_t)(bm + r)*K + k0 + lg*8;
                size_t gb = (size_t)(bn + r)*K + k0 + lg*8;
                cp16(st + so,                 Ahi + ga);
                cp16(st + MAT_BYTES + so,     Alo + ga);
                cp16(st + 2*MAT_BYTES + so,   Bhi + gb);
                cp16(st + 3*MAT_BYTES + so,   Blo + gb);
            }
            CP_COMMIT();
            cp_wait<1>();
        } else {
            cp_wait<0>();
        }
        __syncthreads();

        const char* stg = smem + (c & 1)*STAGE_BYTES;
        const __nv_bfloat16* sAh = (const __nv_bfloat16*)(stg);
        const __nv_bfloat16* sAl = (const __nv_bfloat16*)(stg + MAT_BYTES);
        const __nv_bfloat16* sBh = (const __nv_bfloat16*)(stg + 2*MAT_BYTES);
        const __nv_bfloat16* sBl = (const __nv_bfloat16*)(stg + 3*MAT_BYTES);

#pragma unroll
        for (int ks = 0; ks < 4; ks++) {
            const int kk = ks*16 + (lane & 3)*2;
            unsigned ah[2][4], al[2][4];
#pragma unroll
            for (int ma = 0; ma < 2; ma++) {
                const int r0 = wr*32 + ma*16 + (lane >> 2);
                ah[ma][0] = ld2bf(sAh + r0*PADK + kk);
                ah[ma][1] = ld2bf(sAh + (r0+8)*PADK + kk);
                ah[ma][2] = ld2bf(sAh + r0*PADK + kk + 8);
                ah[ma][3] = ld2bf(sAh + (r0+8)*PADK + kk + 8);
                al[ma][0] = ld2bf(sAl + r0*PADK + kk);
                al[ma][1] = ld2bf(sAl + (r0+8)*PADK + kk);
                al[ma][2] = ld2bf(sAl + r0*PADK + kk + 8);
                al[ma][3] = ld2bf(sAl + (r0+8)*PADK + kk + 8);
            }
            unsigned bh[8][2], bl[8][2];
#pragma unroll
            for (int na = 0; na < 8; na++) {
                const int n0 = wc*64 + na*8 + (lane >> 2);
                bh[na][0] = ld2bf(sBh + n0*PADK + kk);
                bh[na][1] = ld2bf(sBh + n0*PADK + kk + 8);
                bl[na][0] = ld2bf(sBl + n0*PADK + kk);
                bl[na][1] = ld2bf(sBl + n0*PADK + kk + 8);
            }
#pragma unroll
            for (int ma = 0; ma < 2; ma++)
#pragma unroll
                for (int na = 0; na < 8; na++)
                    mma16816(acc[ma][na], ah[ma], bh[na]);
#pragma unroll
            for (int ma = 0; ma < 2; ma++)
#pragma unroll
                for (int na = 0; na < 8; na++)
                    mma16816(acc[ma][na], ah[ma], bl[na]);
#pragma unroll
            for (int ma = 0; ma < 2; ma++)
#pragma unroll
                for (int na = 0; na < 8; na++)
                    mma16816(acc[ma][na], al[ma], bh[na]);
        }
        __syncthreads();
    }

    constexpr bool HASBIAS = (EPI == 1 || EPI == 2);
    constexpr bool RELU    = (EPI == 2);
    constexpr bool PAIR    = (EPI == 2 || EPI == 3);
#pragma unroll
    for (int ma = 0; ma < 2; ma++) {
        const int r0 = bm + wr*32 + ma*16 + (lane >> 2);
#pragma unroll
        for (int na = 0; na < 8; na++) {
            const int cc = bn + wc*64 + na*8 + (lane & 3)*2;
            float v0 = acc[ma][na][0], v1 = acc[ma][na][1];
            float v2 = acc[ma][na][2], v3 = acc[ma][na][3];
            if (HASBIAS) {
                float2 bv = *(const float2*)(bias + cc);
                v0 += bv.x; v1 += bv.y; v2 += bv.x; v3 += bv.y;
            }
            if (RELU) {
                v0 = fmaxf(v0, 0.0f); v1 = fmaxf(v1, 0.0f);
                v2 = fmaxf(v2, 0.0f); v3 = fmaxf(v3, 0.0f);
            }
            if (PAIR) {
                unsigned hi, lo;
                split2(v0, v1, hi, lo);
                *(unsigned*)(Chi + (size_t)r0*N + cc) = hi;
                *(unsigned*)(Clo + (size_t)r0*N + cc) = lo;
                split2(v2, v3, hi, lo);
                *(unsigned*)(Chi + (size_t)(r0+8)*N + cc) = hi;
                *(unsigned*)(Clo + (size_t)(r0+8)*N + cc) = lo;
            } else {
                *(float2*)(Cf + (size_t)r0*N + cc)     = make_float2(v0, v1);
                *(float2*)(Cf + (size_t)(r0+8)*N + cc) = make_float2(v2, v3);
            }
        }
    }
}

// ---------------- V transpose: qkv pair [B,S, V@1024+h*64] -> vt [bh][dh][seq] ----------------
__global__ __launch_bounds__(256) void vtrans_kernel(
    const __nv_bfloat16* __restrict__ qhi, const __nv_bfloat16* __restrict__ qlo,
    __nv_bfloat16* __restrict__ vthi, __nv_bfloat16* __restrict__ vtlo)
{
    __shared__ __nv_bfloat16 th[32][34], tl[32][34];
    const int bh = blockIdx.z, b = bh >> 3, h = bh & 7;
    const int s0 = blockIdx.x*32, d0 = blockIdx.y*32;
    const int tx = threadIdx.x & 31, ty = threadIdx.x >> 5;
#pragma unroll
    for (int i = 0; i < 4; i++) {
        int sr = ty*4 + i;
        size_t g = (size_t)(b*SEQ + s0 + sr)*1536 + 1024 + h*64 + d0 + tx;
        th[sr][tx] = qhi[g];
        tl[sr][tx] = qlo[g];
    }
    __syncthreads();
#pragma unroll
    for (int i = 0; i < 4; i++) {
        int dr = ty*4 + i;
        size_t g = ((size_t)bh*64 + d0 + dr)*1024 + s0 + tx;
        vthi[g] = th[tx][dr];
        vtlo[g] = tl[tx][dr];
    }
}

// ---------------- fused flash attention (split-bf16 mma, online softmax) ----------------
__global__ __launch_bounds__(256, 1) void flash_kernel(
    const __nv_bfloat16* __restrict__ qhi, const __nv_bfloat16* __restrict__ qlo,
    const __nv_bfloat16* __restrict__ vthi, const __nv_bfloat16* __restrict__ vtlo,
    const float* __restrict__ kbias,
    __nv_bfloat16* __restrict__ ohi, __nv_bfloat16* __restrict__ olo)
{
    extern __shared__ char smraw[];
    __nv_bfloat16* sm = (__nv_bfloat16*)smraw;
    const unsigned sb = smem_u32(sm);
    const int tid = threadIdx.x, wid = tid >> 5, lane = tid & 31;
    const int bh = blockIdx.y, b = bh >> 3, h = bh & 7;
    const int q0 = blockIdx.x * 128;
    const int koff = (lane & 3)*2;
    const int r_base = wid*16 + (lane >> 2);

    auto prefetch_kv = [&](int t, int s){
        const int g = tid & 7;
        const int kt0 = t*64;
#pragma unroll
        for (int i = 0; i < 2; i++) {
            int r = (tid >> 3) + i*32;
            size_t gk = (size_t)(b*SEQ + kt0 + r)*1536 + 512 + h*64 + g*8;
            cp16(sb + 2*(KS_HI(s) + r*FPAD + g*8), qhi + gk);
            cp16(sb + 2*(KS_LO(s) + r*FPAD + g*8), qlo + gk);
            size_t gv = ((size_t)bh*64 + r)*1024 + kt0 + g*8;
            cp16(sb + 2*(VS_HI(s) + r*FPAD + g*8), vthi + gv);
            cp16(sb + 2*(VS_LO(s) + r*FPAD + g*8), vtlo + gv);
        }
        if (tid >= 240) {
            int j = tid - 240;
            cp16(sb + 2*BI_F(s) + j*16, kbias + b*SEQ + kt0 + j*4);
        }
    };

    // prefetch Q + tile 0 (commit group 0)
    {
        const int g = tid & 7;
#pragma unroll
        for (int i = 0; i < 4; i++) {
            int r = (tid >> 3) + i*32;
            size_t gq = (size_t)(b*SEQ + q0 + r)*1536 + h*64 + g*8;
            cp16(sb + 2*(Q_HI + r*FPAD + g*8), qhi + gq);
            cp16(sb + 2*(Q_LO + r*FPAD + g*8), qlo + gq);
        }
        prefetch_kv(0, 0);
        CP_COMMIT();
    }

    float m0 = -1e30f, m1 = -1e30f, l0 = 0.0f, l1 = 0.0f;
    float acc_o[8][4];
#pragma unroll
    for (int na = 0; na < 8; na++)
#pragma unroll
        for (int j = 0; j < 4; j++) acc_o[na][j] = 0.0f;

    for (int t = 0; t < NTILE; t++) {
        if (t + 1 < NTILE) { prefetch_kv(t+1, (t+1)&1); CP_COMMIT(); cp_wait<1>(); }
        else               { cp_wait<0>(); }
        __syncthreads();
        const int s = t & 1;
        const __nv_bfloat16* Kh = sm + KS_HI(s);
        const __nv_bfloat16* Kl = sm + KS_LO(s);
        const __nv_bfloat16* Vh = sm + VS_HI(s);
        const __nv_bfloat16* Vl = sm + VS_LO(s);
        const float* bsm = (const float*)(sm + BI_F(s));

        // S = Q K^T (3-product split)
        float sc[8][4];
#pragma unroll
        for (int na = 0; na < 8; na++)
#pragma unroll
            for (int j = 0; j < 4; j++) sc[na][j] = 0.0f;

#pragma unroll
        for (int kc = 0; kc < 4; kc++) {
            const int k2 = kc*16 + koff;
            unsigned ah[4], al[4];
            ah[0] = ld2bf(sm + Q_HI + r_base*FPAD + k2);
            ah[1] = ld2bf(sm + Q_HI + (r_base+8)*FPAD + k2);
            ah[2] = ld2bf(sm + Q_HI + r_base*FPAD + k2 + 8);
            ah[3] = ld2bf(sm + Q_HI + (r_base+8)*FPAD + k2 + 8);
            al[0] = ld2bf(sm + Q_LO + r_base*FPAD + k2);
            al[1] = ld2bf(sm + Q_LO + (r_base+8)*FPAD + k2);
            al[2] = ld2bf(sm + Q_LO + r_base*FPAD + k2 + 8);
            al[3] = ld2bf(sm + Q_LO + (r_base+8)*FPAD + k2 + 8);
#pragma unroll
            for (int na = 0; na < 8; na++) {
                const int n = na*8 + (lane >> 2);
                unsigned bh2[2], bl2[2];
                bh2[0] = ld2bf(Kh + n*FPAD + k2);
                bh2[1] = ld2bf(Kh + n*FPAD + k2 + 8);
                bl2[0] = ld2bf(Kl + n*FPAD + k2);
                bl2[1] = ld2bf(Kl + n*FPAD + k2 + 8);
                mma16816(sc[na], ah, bh2);
                mma16816(sc[na], ah, bl2);
                mma16816(sc[na], al, bh2);
            }
        }

        // key-mask bias
#pragma unroll
        for (int na = 0; na < 8; na++) {
            float b0 = bsm[na*8 + koff], b1 = bsm[na*8 + koff + 1];
            sc[na][0] += b0; sc[na][1] += b1;
            sc[na][2] += b0; sc[na][3] += b1;
        }

        // online softmax (rows r_base and r_base+8)
        float mx0 = -1e30f, mx1 = -1e30f;
#pragma unroll
        for (int na = 0; na < 8; na++) {
            mx0 = fmaxf(mx0, fmaxf(sc[na][0], sc[na][1]));
            mx1 = fmaxf(mx1, fmaxf(sc[na][2], sc[na][3]));
        }
        mx0 = fmaxf(mx0, __shfl_xor_sync(0xffffffffu, mx0, 1));
        mx0 = fmaxf(mx0, __shfl_xor_sync(0xffffffffu, mx0, 2));
        mx1 = fmaxf(mx1, __shfl_xor_sync(0xffffffffu, mx1, 1));
        mx1 = fmaxf(mx1, __shfl_xor_sync(0xffffffffu, mx1, 2));
        float mn0 = fmaxf(m0, mx0), mn1 = fmaxf(m1, mx1);
        float e0 = __expf(m0 - mn0), e1 = __expf(m1 - mn1);
        m0 = mn0; m1 = mn1;
        float s0 = 0.0f, s1 = 0.0f;
#pragma unroll
        for (int na = 0; na < 8; na++) {
            sc[na][0] = __expf(sc[na][0] - mn0);
            sc[na][1] = __expf(sc[na][1] - mn0);
            sc[na][2] = __expf(sc[na][2] - mn1);
            sc[na][3] = __expf(sc[na][3] - mn1);
            s0 += sc[na][0] + sc[na][1];
            s1 += sc[na][2] + sc[na][3];
        }
        s0 += __shfl_xor_sync(0xffffffffu, s0, 1);
        s0 += __shfl_xor_sync(0xffffffffu, s0, 2);
        s1 += __shfl_xor_sync(0xffffffffu, s1, 1);
        s1 += __shfl_xor_sync(0xffffffffu, s1, 2);
        l0 = l0*e0 + s0;
        l1 = l1*e1 + s1;
#pragma unroll
        for (int na = 0; na < 8; na++) {
            acc_o[na][0] *= e0; acc_o[na][1] *= e0;
            acc_o[na][2] *= e1; acc_o[na][3] *= e1;
        }

        // O += P V (3-product split; P frags from registers)
#pragma unroll
        for (int kc = 0; kc < 4; kc++) {
            unsigned ph[4], pl[4];
            split2(sc[2*kc][0],   sc[2*kc][1],   ph[0], pl[0]);
            split2(sc[2*kc][2],   sc[2*kc][3],   ph[1], pl[1]);
            split2(sc[2*kc+1][0], sc[2*kc+1][1], ph[2], pl[2]);
            split2(sc[2*kc+1][2], sc[2*kc+1][3], ph[3], pl[3]);
            const int k2 = kc*16 + koff;
#pragma unroll
            for (int na = 0; na < 8; na++) {
                const int n = na*8 + (lane >> 2);
                unsigned vh2[2], vl2[2];
                vh2[0] = ld2bf(Vh + n*FPAD + k2);
                vh2[1] = ld2bf(Vh + n*FPAD + k2 + 8);
                vl2[0] = ld2bf(Vl + n*FPAD + k2);
                vl2[1] = ld2bf(Vl + n*FPAD + k2 + 8);
                mma16816(acc_o[na], ph, vh2);
                mma16816(acc_o[na], ph, vl2);
                mma16816(acc_o[na], pl, vh2);
            }
        }
        __syncthreads();
    }

    // epilogue: O /= l, write bf16 hi/lo pair at [b, q0+row, h*64+col]
    const float inv0 = 1.0f / l0, inv1 = 1.0f / l1;
    const size_t row0 = (size_t)(b*SEQ + q0 + r_base);
#pragma unroll
    for (int na = 0; na < 8; na++) {
        const int col = h*64 + na*8 + koff;
        unsigned hi, lo;
        split2(acc_o[na][0]*inv0, acc_o[na][1]*inv0, hi, lo);
        *(unsigned*)(ohi + row0*DMODEL + col) = hi;
        *(unsigned*)(olo + row0*DMODEL + col) = lo;
        split2(acc_o[na][2]*inv1, acc_o[na][3]*inv1, hi, lo);
        *(unsigned*)(ohi + (row0+8)*DMODEL + col) = hi;
        *(unsigned*)(olo + (row0+8)*DMODEL + col) = lo;
    }
}

// ---------------- positional embedding + pair split + key-mask bias ----------------
__global__ void posembed_kernel(const float* __restrict__ xin,
                                const int* __restrict__ mask,
                                float* __restrict__ xout,
                                __nv_bfloat16* __restrict__ xhi,
                                __nv_bfloat16* __restrict__ xlo,
                                float* __restrict__ kb)
{
    int b = blockIdx.x;
    int tid = threadIdx.x;                    // 1024 threads
    __shared__ int sc[SEQ];
    int valid = (mask[b*SEQ + tid] != 0) ? 1 : 0;
    kb[b*SEQ + tid] = valid ? 0.0f : -1e30f;
    sc[tid] = valid;
    __syncthreads();
    for (int off = 1; off < SEQ; off <<= 1) {
        int v = (tid >= off) ? sc[tid - off] : 0;
        __syncthreads();
        sc[tid] += v;
        __syncthreads();
    }
    int pos = sc[tid] * valid;
    __syncthreads();
    sc[tid] = pos;
    __syncthreads();

    const float cfreq = -logf(10000.0f) / 255.0f;
    for (int it = 0; it < (SEQ*DMODEL)/SEQ; it++) {
        int idx = it*SEQ + tid;
        int s = idx >> 9;
        int j = idx & 511;
        int p = sc[s];
        size_t g = ((size_t)b*SEQ + s)*DMODEL + j;
        float add = 0.0f;
        if (p > 0) {
            float fr  = expf((float)(j & 255) * cfreq);
            float ang = (float)p * fr;
            add = (j < 256) ? sinf(ang) : cosf(ang);
        }
        float v = xin[g] + add;
        xout[g] = v;
        __nv_bfloat16 h, l; split_bf16(v, h, l);
        xhi[g] = h; xlo[g] = l;
    }
}

// ---------------- out = LN(a + r) * g + b ; also emits bf16 pair ----------------
__global__ __launch_bounds__(256) void ln_kernel(
    const float* __restrict__ a, const float* __restrict__ r,
    const float* __restrict__ g, const float* __restrict__ be,
    float* __restrict__ out,
    __nv_bfloat16* __restrict__ ohi, __nv_bfloat16* __restrict__ olo)
{
    int row = blockIdx.x;
    int tid = threadIdx.x;
    __shared__ float red[256];
    size_t base = (size_t)row*DMODEL + tid*2;
    float2 va = *(const float2*)(a + base);
    float2 vr = *(const float2*)(r + base);
    float x0 = va.x + vr.x, x1 = va.y + vr.y;
    red[tid] = x0 + x1; __syncthreads();
    for (int off = 128; off; off >>= 1) {
        if (tid < off) red[tid] += red[tid + off];
        __syncthreads();
    }
    float mu = red[0] * (1.0f/512.0f); __syncthreads();
    float d0 = x0 - mu, d1 = x1 - mu;
    red[tid] = d0*d0 + d1*d1; __syncthreads();
    for (int off = 128; off; off >>= 1) {
        if (tid < off) red[tid] += red[tid + off];
        __syncthreads();
    }
    float inv = rsqrtf(red[0] * (1.0f/512.0f) + 1e-5f);
    float2 gg = *(const float2*)(g + tid*2);
    float2 bb = *(const float2*)(be + tid*2);
    float o0 = d0*inv*gg.x + bb.x;
    float o1 = d1*inv*gg.y + bb.y;
    *(float2*)(out + base) = make_float2(o0, o1);
    unsigned hi, lo;
    split2(o0, o1, hi, lo);
    *(unsigned*)(ohi + base) = hi;
    *(unsigned*)(olo + base) = lo;
}

// ---------------- driver ----------------
extern "C" void kernel_launch(void* const* d_in, const int* in_sizes, int n_in,
                              void* d_out, int out_size)
{
    const float* x_in = (const float*)d_in[0];
    const int*   mask = (const int*)d_in[3];
    const float* Wqkv = (const float*)d_in[4];
    const float* Wfc  = (const float*)d_in[5];
    const float* bfc  = (const float*)d_in[6];
    const float* ln1g = (const float*)d_in[7];
    const float* ln1b = (const float*)d_in[8];
    const float* ln2g = (const float*)d_in[9];
    const float* ln2b = (const float*)d_in[10];
    const float* W1   = (const float*)d_in[11];
    const float* b1   = (const float*)d_in[12];
    const float* W2   = (const float*)d_in[13];
    const float* b2   = (const float*)d_in[14];

    float *px, *ptmp, *pkb;
    __nv_bfloat16 *pxhi, *pxlo, *pqh, *pql, *pvth, *pvtl, *paohi, *paolo, *pfhi, *pflo;
    __nv_bfloat16 *wqh, *wql, *wfh, *wfl, *w1h, *w1l, *w2h, *w2l;
    cudaGetSymbolAddress((void**)&px,    g_x);
    cudaGetSymbolAddress((void**)&pxhi,  g_xhi);
    cudaGetSymbolAddress((void**)&pxlo,  g_xlo);
    cudaGetSymbolAddress((void**)&pqh,   g_qkvhi);
    cudaGetSymbolAddress((void**)&pql,   g_qkvlo);
    cudaGetSymbolAddress((void**)&pvth,  g_vthi);
    cudaGetSymbolAddress((void**)&pvtl,  g_vtlo);
    cudaGetSymbolAddress((void**)&pkb,   g_kbias);
    cudaGetSymbolAddress((void**)&paohi, g_aohi);
    cudaGetSymbolAddress((void**)&paolo, g_aolo);
    cudaGetSymbolAddress((void**)&ptmp,  g_tmp);
    cudaGetSymbolAddress((void**)&pfhi,  g_fhi);
    cudaGetSymbolAddress((void**)&pflo,  g_flo);
    cudaGetSymbolAddress((void**)&wqh,   g_wqkvhi);
    cudaGetSymbolAddress((void**)&wql,   g_wqkvlo);
    cudaGetSymbolAddress((void**)&wfh,   g_wfchi);
    cudaGetSymbolAddress((void**)&wfl,   g_wfclo);
    cudaGetSymbolAddress((void**)&w1h,   g_w1hi);
    cudaGetSymbolAddress((void**)&w1l,   g_w1lo);
    cudaGetSymbolAddress((void**)&w2h,   g_w2hi);
    cudaGetSymbolAddress((void**)&w2l,   g_w2lo);

    cudaFuncSetAttribute(mma_gemm_kernel<0>, cudaFuncAttributeMaxDynamicSharedMemorySize, GEMM_SMEM);
    cudaFuncSetAttribute(mma_gemm_kernel<1>, cudaFuncAttributeMaxDynamicSharedMemorySize, GEMM_SMEM);
    cudaFuncSetAttribute(mma_gemm_kernel<2>, cudaFuncAttributeMaxDynamicSharedMemorySize, GEMM_SMEM);
    cudaFuncSetAttribute(mma_gemm_kernel<3>, cudaFuncAttributeMaxDynamicSharedMemorySize, GEMM_SMEM);
    cudaFuncSetAttribute(flash_kernel, cudaFuncAttributeMaxDynamicSharedMemorySize, FLASH_SMEM);

    // weight prep: tiled transpose + split, all layers per launch
    wprep_kernel<<<dim3(3*DMODEL/32, DMODEL/32, NLAYER), 256>>>(Wqkv, wqh, wql, DMODEL, 3*DMODEL);
    wprep_kernel<<<dim3(DMODEL/32,   DMODEL/32, NLAYER), 256>>>(Wfc,  wfh, wfl, DMODEL, DMODEL);
    wprep_kernel<<<dim3(DFF/32,      DMODEL/32, NLAYER), 256>>>(W1,   w1h, w1l, DMODEL, DFF);
    wprep_kernel<<<dim3(DMODEL/32,   DFF/32,    NLAYER), 256>>>(W2,   w2h, w2l, DFF, DMODEL);

    posembed_kernel<<<BATCH, SEQ>>>(x_in, mask, px, pxhi, pxlo, pkb);

    for (int l = 0; l < NLAYER; l++) {
        size_t oq = (size_t)l*3*DMODEL*DMODEL;
        size_t of = (size_t)l*DMODEL*DMODEL;
        size_t o1 = (size_t)l*DFF*DMODEL;
        size_t o2 = (size_t)l*DMODEL*DFF;
        // QKV -> bf16 hi/lo pair
        mma_gemm_kernel<3><<<dim3(3*DMODEL/TN, NTOK/TM), 256, GEMM_SMEM>>>(
            pxhi, pxlo, wqh + oq, wql + oq, nullptr, nullptr, pqh, pql, 3*DMODEL, DMODEL);
        // V transpose for flash B-operand
        vtrans_kernel<<<dim3(SEQ/32, DHEAD/32, BATCH*NHEAD), 256>>>(pqh, pql, pvth, pvtl);
        // fused attention
        flash_kernel<<<dim3(SEQ/128, BATCH*NHEAD), 256, FLASH_SMEM>>>(
            pqh, pql, pvth, pvtl, pkb, paohi, paolo);
        // proj + bias -> fp32
        mma_gemm_kernel<1><<<dim3(DMODEL/TN, NTOK/TM), 256, GEMM_SMEM>>>(
            paohi, paolo, wfh + of, wfl + of, bfc + l*DMODEL, ptmp, nullptr, nullptr, DMODEL, DMODEL);
        ln_kernel<<<NTOK, 256>>>(ptmp, px, ln1g + l*DMODEL, ln1b + l*DMODEL, px, pxhi, pxlo);
        // FFN up + relu -> bf16 pair
        mma_gemm_kernel<2><<<dim3(DFF/TN, NTOK/TM), 256, GEMM_SMEM>>>(
            pxhi, pxlo, w1h + o1, w1l + o1, b1 + l*DFF, nullptr, pfhi, pflo, DFF, DMODEL);
        // FFN down + bias -> fp32
        mma_gemm_kernel<1><<<dim3(DMODEL/TN, NTOK/TM), 256, GEMM_SMEM>>>(
            pfhi, pflo, w2h + o2, w2l + o2, b2 + l*DMODEL, ptmp, nullptr, nullptr, DMODEL, DFF);
        ln_kernel<<<NTOK, 256>>>(ptmp, px, ln2g + l*DMODEL, ln2b + l*DMODEL, px, pxhi, pxlo);
    }

    cudaMemcpyAsync(d_out, px, (size_t)NTOK*DMODEL*sizeof(float),
                    cudaMemcpyDeviceToDevice);
}